// round 1
// baseline (speedup 1.0000x reference)
#include <cuda_runtime.h>

#define NN    4096
#define FIN   256
#define FOUT  64
#define HEADS 4
#define NF    (NN * FOUT)   // 262144

// ---------------- device scratch (no allocations allowed) ----------------
__device__ float g_h[NN * FIN];          // x @ W, row-major [n][head*64+f]
__device__ float g_ei[NN * HEADS];
__device__ float g_ej[NN * HEADS];
__device__ float g_part[HEADS * NN * FOUT];  // per-head normalized output

// packed f32x2 FMA (Blackwell): d = a*b + d, lanewise on 2 packed floats
#define FMA2(d, a, b) asm("fma.rn.f32x2 %0, %1, %2, %0;" : "+l"(d) : "l"(a), "l"(b))

// ---------------- kernel 1: h = x @ W  (4096x256 @ 256x256) --------------
__global__ void __launch_bounds__(256) gemm_h_kernel(const float* __restrict__ x,
                                                     const float* __restrict__ W) {
    __shared__ float xs[32][FIN];
    const int n0 = blockIdx.x * 32;
    const int t  = threadIdx.x;

    #pragma unroll
    for (int r = 0; r < 32; ++r) xs[r][t] = x[(n0 + r) * FIN + t];
    __syncthreads();

    float acc[32];
    #pragma unroll
    for (int r = 0; r < 32; ++r) acc[r] = 0.0f;

    for (int k = 0; k < FIN; k += 4) {
        const float w0 = W[(k + 0) * 256 + t];
        const float w1 = W[(k + 1) * 256 + t];
        const float w2 = W[(k + 2) * 256 + t];
        const float w3 = W[(k + 3) * 256 + t];
        #pragma unroll
        for (int r = 0; r < 32; ++r) {
            const float4 xv = *(const float4*)&xs[r][k];
            acc[r] = fmaf(xv.x, w0, acc[r]);
            acc[r] = fmaf(xv.y, w1, acc[r]);
            acc[r] = fmaf(xv.z, w2, acc[r]);
            acc[r] = fmaf(xv.w, w3, acc[r]);
        }
    }
    #pragma unroll
    for (int r = 0; r < 32; ++r) g_h[(n0 + r) * FIN + t] = acc[r];
}

// ---------------- kernel 2: e_i / e_j per (node, head) -------------------
__global__ void __launch_bounds__(256) escore_kernel(const float* __restrict__ a) {
    __shared__ float s1[256], s2[256];
    const int n = blockIdx.x;
    const int t = threadIdx.x;
    const int ff = t & 63;
    const float v = g_h[n * FIN + t];
    s1[t] = v * a[ff];
    s2[t] = v * a[64 + ff];
    __syncthreads();
    #pragma unroll
    for (int off = 32; off >= 1; off >>= 1) {
        if ((t & 63) < off) { s1[t] += s1[t + off]; s2[t] += s2[t + off]; }
        __syncthreads();
    }
    if ((t & 63) == 0) {
        const int hd = t >> 6;
        g_ei[n * HEADS + hd] = s1[t];
        g_ej[n * HEADS + hd] = s2[t];
    }
}

// ---------------- kernel 3: fused masked-softmax attention ---------------
// Block = 64 output rows x 1 head. Tile over j (32). Weight tile generated
// on the fly from adj + e_i + e_j; exact fp32 accumulation via fma.rn.f32x2.
__global__ void __launch_bounds__(256) gat_attn_kernel(const int* __restrict__ adj) {
    const int hd = blockIdx.y;
    const int i0 = blockIdx.x * 64;

    __shared__ float  eis[64];
    __shared__ float2 ws[32 * 66];   // [jj][ii] duplicated pair {w,w}, stride 66 (16B align, pad)
    __shared__ float  hs[32 * 64];   // [jj][ff]
    __shared__ float  zsm[64];

    const int t    = threadIdx.x;
    const int lane = t & 31;
    const int wid  = t >> 5;

    if (t < 64) eis[t] = g_ei[(i0 + t) * HEADS + hd];

    // GEMM-phase mapping: 4 rows x 4 cols per thread
    const int ii0 = (t >> 4) * 4;
    const int ff0 = (t & 15) * 4;

    unsigned long long acc[4][2];
    #pragma unroll
    for (int i = 0; i < 4; ++i) { acc[i][0] = 0ull; acc[i][1] = 0ull; }
    float z[8];
    #pragma unroll
    for (int k = 0; k < 8; ++k) z[k] = 0.0f;

    const float* hcol = g_h + hd * FOUT;
    const int jA = t >> 4;         // 0..15 (h-tile row for loads)
    const int c4 = (t & 15) * 4;   // 0..60

    __syncthreads();  // eis ready

    for (int j0 = 0; j0 < NN; j0 += 32) {
        // --- load h tile (32 x 64) straight to registers, coalesced ---
        const float4 hv0 = *(const float4*)&hcol[(j0 + jA) * FIN + c4];
        const float4 hv1 = *(const float4*)&hcol[(j0 + 16 + jA) * FIN + c4];

        // --- generate weight tile: jj = lane, ii = wid + 8k ---
        const float ejv = g_ej[(j0 + lane) * HEADS + hd];
        const int* arow = adj + (size_t)(i0 + wid) * NN + j0 + lane;
        #pragma unroll
        for (int k = 0; k < 8; ++k) {
            const int ii = wid + 8 * k;
            const float s = eis[ii] + ejv;
            const float l = s > 0.0f ? s : 0.2f * s;
            const int av  = arow[(size_t)(8 * k) * NN];
            const float w = av ? __expf(l) : 0.0f;
            z[k] += w;
            ws[lane * 66 + ii] = make_float2(w, w);
        }
        *(float4*)&hs[jA * 64 + c4]        = hv0;
        *(float4*)&hs[(jA + 16) * 64 + c4] = hv1;
        __syncthreads();

        // --- 4x4 register-tile accumulation, packed f32x2 ---
        #pragma unroll
        for (int jj = 0; jj < 32; ++jj) {
            const ulonglong2 a01 = *(const ulonglong2*)&ws[jj * 66 + ii0];
            const ulonglong2 a23 = *(const ulonglong2*)&ws[jj * 66 + ii0 + 2];
            const ulonglong2 bv  = *(const ulonglong2*)&hs[jj * 64 + ff0];
            FMA2(acc[0][0], a01.x, bv.x);  FMA2(acc[0][1], a01.x, bv.y);
            FMA2(acc[1][0], a01.y, bv.x);  FMA2(acc[1][1], a01.y, bv.y);
            FMA2(acc[2][0], a23.x, bv.x);  FMA2(acc[2][1], a23.x, bv.y);
            FMA2(acc[3][0], a23.y, bv.x);  FMA2(acc[3][1], a23.y, bv.y);
        }
        __syncthreads();
    }

    // --- reduce Z across the 32 jj-lanes of each warp ---
    #pragma unroll
    for (int k = 0; k < 8; ++k) {
        float v = z[k];
        #pragma unroll
        for (int off = 16; off >= 1; off >>= 1)
            v += __shfl_down_sync(0xffffffffu, v, off);
        if (lane == 0) zsm[wid + 8 * k] = v;
    }
    __syncthreads();

    // --- epilogue: normalize and store per-head partial ---
    float* po = g_part + ((size_t)hd * NN + i0) * FOUT;
    #pragma unroll
    for (int i = 0; i < 4; ++i) {
        const float invz = 1.0f / zsm[ii0 + i];
        union { unsigned long long u; float2 f; } lo, hi;
        lo.u = acc[i][0];
        hi.u = acc[i][1];
        const float4 o = make_float4(lo.f.x * invz, lo.f.y * invz,
                                     hi.f.x * invz, hi.f.y * invz);
        *(float4*)&po[(ii0 + i) * FOUT + ff0] = o;
    }
}

// ---------------- kernel 4: mean over heads -------------------------------
__global__ void __launch_bounds__(256) combine_kernel(float* __restrict__ out) {
    const int idx = blockIdx.x * 256 + threadIdx.x;
    const float s = g_part[idx] + g_part[NF + idx] +
                    g_part[2 * NF + idx] + g_part[3 * NF + idx];
    out[idx] = 0.25f * s;
}

// ---------------- launcher ------------------------------------------------
extern "C" void kernel_launch(void* const* d_in, const int* in_sizes, int n_in,
                              void* d_out, int out_size) {
    // Resolve inputs by element count (robust to ordering):
    // x: 4096*256 = 1048576, adj: 4096*4096 = 16777216, W: 256*256 = 65536, a: 128
    const float* x = nullptr;
    const int*   adj = nullptr;
    const float* W = nullptr;
    const float* a = nullptr;
    for (int i = 0; i < n_in; ++i) {
        switch (in_sizes[i]) {
            case 1048576:  x   = (const float*)d_in[i]; break;
            case 16777216: adj = (const int*)  d_in[i]; break;
            case 65536:    W   = (const float*)d_in[i]; break;
            case 128:      a   = (const float*)d_in[i]; break;
        }
    }
    float* out = (float*)d_out;

    gemm_h_kernel<<<NN / 32, 256>>>(x, W);
    escore_kernel<<<NN, 256>>>(a);
    gat_attn_kernel<<<dim3(NN / 64, HEADS), 256>>>(adj);
    combine_kernel<<<NF / 256, 256>>>(out);
}

// round 3
// speedup vs baseline: 1.3407x; 1.3407x over previous
#include <cuda_runtime.h>

#define NN      4096
#define FIN     256
#define FOUT    64
#define HEADS   4
#define NSPLIT  8
#define I_TILE  512
#define J_TILE  16
#define J_RANGE (NN / NSPLIT)          // 512
#define N_JTILES (J_RANGE / J_TILE)    // 32
#define WSTRIDE (I_TILE + 4)           // 516 floats (x4B = 2064B, 16B-aligned)

// ---------------- device scratch ----------------
__device__ float  g_h[NN * FIN];                       // x @ W
__device__ float4 g_i4[NN * HEADS];                    // {ei, exp(ei), exp(.2ei), 0}
__device__ float4 g_j4[NN * HEADS];                    // {ej, exp(ej), exp(.2ej), 0}
__device__ float  g_c[HEADS * NSPLIT * NN * FOUT];     // partial numerators (32MB)
__device__ float  g_z[HEADS * NSPLIT * NN];            // partial denominators

#define FMA2(d, a, b) asm("fma.rn.f32x2 %0, %1, %2, %0;" : "+l"(d) : "l"(a), "l"(b))
#define ADD2(d, a)    asm("add.rn.f32x2 %0, %1, %0;"     : "+l"(d) : "l"(a))

__device__ __forceinline__ unsigned long long dup2(float v) {
    unsigned long long r;
    asm("mov.b64 %0, {%1, %1};" : "=l"(r) : "r"(__float_as_uint(v)));
    return r;
}

// ---------------- kernel 1: h = x @ W ----------------
__global__ void __launch_bounds__(256) gemm_h_kernel(const float* __restrict__ x,
                                                     const float* __restrict__ W) {
    __shared__ float xs[32][FIN];
    const int n0 = blockIdx.x * 32;
    const int t  = threadIdx.x;

    #pragma unroll
    for (int r = 0; r < 32; ++r) xs[r][t] = x[(n0 + r) * FIN + t];
    __syncthreads();

    float acc[32];
    #pragma unroll
    for (int r = 0; r < 32; ++r) acc[r] = 0.0f;

    for (int k = 0; k < FIN; k += 4) {
        const float w0 = W[(k + 0) * 256 + t];
        const float w1 = W[(k + 1) * 256 + t];
        const float w2 = W[(k + 2) * 256 + t];
        const float w3 = W[(k + 3) * 256 + t];
        #pragma unroll
        for (int r = 0; r < 32; ++r) {
            const float4 xv = *(const float4*)&xs[r][k];
            acc[r] = fmaf(xv.x, w0, acc[r]);
            acc[r] = fmaf(xv.y, w1, acc[r]);
            acc[r] = fmaf(xv.z, w2, acc[r]);
            acc[r] = fmaf(xv.w, w3, acc[r]);
        }
    }
    #pragma unroll
    for (int r = 0; r < 32; ++r) g_h[(n0 + r) * FIN + t] = acc[r];
}

// ---------------- kernel 2: e scores + factored exps ----------------
__global__ void __launch_bounds__(256) escore_kernel(const float* __restrict__ a) {
    __shared__ float s1[256], s2[256];
    const int n = blockIdx.x;
    const int t = threadIdx.x;
    const int ff = t & 63;
    const float v = g_h[n * FIN + t];
    s1[t] = v * a[ff];
    s2[t] = v * a[64 + ff];
    __syncthreads();
    #pragma unroll
    for (int off = 32; off >= 1; off >>= 1) {
        if ((t & 63) < off) { s1[t] += s1[t + off]; s2[t] += s2[t + off]; }
        __syncthreads();
    }
    if ((t & 63) == 0) {
        const int hd = t >> 6;
        const float ei = s1[t], ej = s2[t];
        g_i4[n * HEADS + hd] = make_float4(ei, __expf(ei), __expf(0.2f * ei), 0.0f);
        g_j4[n * HEADS + hd] = make_float4(ej, __expf(ej), __expf(0.2f * ej), 0.0f);
    }
}

// ---------------- kernel 3: fused masked-softmax attention ----------------
// Block: i_tile=512 rows x 64 ff x 1 head x 1 j-split (512 j's as 32 tiles of 16).
// Per-thread register tile: 16 rows x 8 cols as f32x2 row-pairs (exact fp32).
__global__ void __launch_bounds__(256, 1) gat_attn_kernel(const int* __restrict__ adj) {
    const int head  = blockIdx.y;
    const int i0    = blockIdx.x * I_TILE;
    const int split = blockIdx.z;
    const int j0base = split * J_RANGE;

    __shared__ float  ws[J_TILE * WSTRIDE];   // w[jj][ii], ~33KB
    __shared__ float  hs[J_TILE * 64];        // h[jj][ff], 4KB
    __shared__ float4 esm[I_TILE];            // {ei, EPi, ENi, 0}, 8KB

    const int t = threadIdx.x;

    esm[t]       = g_i4[(i0 + t) * HEADS + head];
    esm[t + 256] = g_i4[(i0 + t + 256) * HEADS + head];

    // GEMM coords: 8 ff-threads x 32 ii-groups
    const int ff_t = t & 7;
    const int ii_t = t >> 3;
    const int ii0  = ii_t * 16;

    // gen coords: 16 jj-threads x 16 row-groups
    const int tj = t & 15;
    const int rg = t >> 4;

    unsigned long long acc[8][8];
    #pragma unroll
    for (int p = 0; p < 8; ++p)
        #pragma unroll
        for (int f = 0; f < 8; ++f) acc[p][f] = 0ull;
    unsigned long long zp = 0ull;   // z pair for rows {2t, 2t+1}

    const float* hsrc = g_h + head * FOUT;

    __syncthreads();   // esm ready before any cross-thread read (round-2 bug fix)

    for (int jt = 0; jt < N_JTILES; ++jt) {
        const int j0 = j0base + jt * J_TILE;

        // ---- generate weight tile w[jj][ii] (factored exp, no MUFU) ----
        const float4 jd = g_j4[(j0 + tj) * HEADS + head];
        const int* acol = adj + (size_t)(i0 + 2 * rg) * NN + (j0 + tj);
        #pragma unroll
        for (int k = 0; k < 16; ++k) {
            const int r0 = 32 * k + 2 * rg;
            const float4 d0 = esm[r0];
            const float4 d1 = esm[r0 + 1];
            const int a0 = acol[(size_t)(32 * k) * NN];
            const int a1 = acol[(size_t)(32 * k + 1) * NN];
            float w0 = (d0.x + jd.x > 0.0f) ? d0.y * jd.y : d0.z * jd.z;
            float w1 = (d1.x + jd.x > 0.0f) ? d1.y * jd.y : d1.z * jd.z;
            w0 = a0 ? w0 : 0.0f;
            w1 = a1 ? w1 : 0.0f;
            *(float2*)&ws[tj * WSTRIDE + r0] = make_float2(w0, w1);
        }
        // ---- h tile: 16 rows x 64 cols ----
        {
            const int hr = t >> 4;
            const int hc = (t & 15) * 4;
            *(float4*)&hs[hr * 64 + hc] =
                *(const float4*)&hsrc[(size_t)(j0 + hr) * FIN + hc];
        }
        __syncthreads();

        // ---- Z partial: each thread owns rows {2t, 2t+1} ----
        #pragma unroll
        for (int jj = 0; jj < J_TILE; ++jj) {
            const unsigned long long w01 =
                *(const unsigned long long*)&ws[jj * WSTRIDE + 2 * t];
            ADD2(zp, w01);
        }

        // ---- GEMM: 16 rows (8 pairs) x 8 ff per thread ----
        #pragma unroll 4
        for (int jj = 0; jj < J_TILE; ++jj) {
            const float4 h0 = *(const float4*)&hs[jj * 64 + ff_t * 8];
            const float4 h1 = *(const float4*)&hs[jj * 64 + ff_t * 8 + 4];
            unsigned long long hh[8];
            hh[0] = dup2(h0.x); hh[1] = dup2(h0.y);
            hh[2] = dup2(h0.z); hh[3] = dup2(h0.w);
            hh[4] = dup2(h1.x); hh[5] = dup2(h1.y);
            hh[6] = dup2(h1.z); hh[7] = dup2(h1.w);
            const ulonglong2 wA = *(const ulonglong2*)&ws[jj * WSTRIDE + ii0];
            const ulonglong2 wB = *(const ulonglong2*)&ws[jj * WSTRIDE + ii0 + 4];
            const ulonglong2 wC = *(const ulonglong2*)&ws[jj * WSTRIDE + ii0 + 8];
            const ulonglong2 wD = *(const ulonglong2*)&ws[jj * WSTRIDE + ii0 + 12];
            const unsigned long long wp[8] =
                { wA.x, wA.y, wB.x, wB.y, wC.x, wC.y, wD.x, wD.y };
            #pragma unroll
            for (int p = 0; p < 8; ++p)
                #pragma unroll
                for (int f = 0; f < 8; ++f)
                    FMA2(acc[p][f], wp[p], hh[f]);
        }
        __syncthreads();
    }

    // ---- epilogue: store partial C and partial Z ----
    float* cb = g_c + ((size_t)(head * NSPLIT + split) * NN + i0) * FOUT;
    #pragma unroll
    for (int p = 0; p < 8; ++p) {
        union { unsigned long long u; float2 f; } v[8];
        #pragma unroll
        for (int f = 0; f < 8; ++f) v[f].u = acc[p][f];
        const int r0 = ii0 + 2 * p;
        const float4 lo0 = make_float4(v[0].f.x, v[1].f.x, v[2].f.x, v[3].f.x);
        const float4 lo1 = make_float4(v[4].f.x, v[5].f.x, v[6].f.x, v[7].f.x);
        const float4 hi0 = make_float4(v[0].f.y, v[1].f.y, v[2].f.y, v[3].f.y);
        const float4 hi1 = make_float4(v[4].f.y, v[5].f.y, v[6].f.y, v[7].f.y);
        *(float4*)&cb[(size_t)r0 * FOUT + ff_t * 8]           = lo0;
        *(float4*)&cb[(size_t)r0 * FOUT + ff_t * 8 + 4]       = lo1;
        *(float4*)&cb[(size_t)(r0 + 1) * FOUT + ff_t * 8]     = hi0;
        *(float4*)&cb[(size_t)(r0 + 1) * FOUT + ff_t * 8 + 4] = hi1;
    }
    {
        union { unsigned long long u; float2 f; } zz; zz.u = zp;
        *(float2*)&g_z[(size_t)(head * NSPLIT + split) * NN + i0 + 2 * t] = zz.f;
    }
}

// ---------------- kernel 4: combine splits, normalize, mean heads ----------
__global__ void __launch_bounds__(256) combine_kernel(float* __restrict__ out) {
    const int idx = blockIdx.x * 256 + threadIdx.x;   // i*64 + f
    const int i = idx >> 6;
    const int f = idx & 63;
    float r = 0.0f;
    #pragma unroll
    for (int h = 0; h < HEADS; ++h) {
        float c = 0.0f, z = 0.0f;
        #pragma unroll
        for (int s = 0; s < NSPLIT; ++s) {
            c += g_c[((size_t)(h * NSPLIT + s) * NN + i) * FOUT + f];
            z += g_z[(size_t)(h * NSPLIT + s) * NN + i];
        }
        r += c / z;
    }
    out[idx] = 0.25f * r;
}

// ---------------- launcher ----------------
extern "C" void kernel_launch(void* const* d_in, const int* in_sizes, int n_in,
                              void* d_out, int out_size) {
    const float* x = nullptr;
    const int*   adj = nullptr;
    const float* W = nullptr;
    const float* a = nullptr;
    for (int i = 0; i < n_in; ++i) {
        switch (in_sizes[i]) {
            case 1048576:  x   = (const float*)d_in[i]; break;
            case 16777216: adj = (const int*)  d_in[i]; break;
            case 65536:    W   = (const float*)d_in[i]; break;
            case 128:      a   = (const float*)d_in[i]; break;
        }
    }
    float* out = (float*)d_out;

    gemm_h_kernel<<<NN / 32, 256>>>(x, W);
    escore_kernel<<<NN, 256>>>(a);
    gat_attn_kernel<<<dim3(NN / I_TILE, HEADS, NSPLIT), 256>>>(adj);
    combine_kernel<<<(NN * FOUT) / 256, 256>>>(out);
}

// round 5
// speedup vs baseline: 2.9808x; 2.2233x over previous
#include <cuda_runtime.h>
#include <cuda_fp16.h>
#include <cstdint>

#define NN      4096
#define FIN     256
#define FOUT    64
#define HEADS   4
#define NF      (NN * FOUT)
#define ITILE   64
#define JCHUNK  64
#define NCHUNK  (NN / JCHUNK)   // 64
#define ADJW    (NN / 32)       // 128 words per adj row

// ---------------- device scratch ----------------
__device__ float    g_h[NN * FIN];               // x @ W (fp32, for escore)
__device__ float4   g_i4[NN * HEADS];            // {ei, exp(ei), exp(.2ei), 0}
__device__ float4   g_j4[NN * HEADS];            // {ej, exp(ej), exp(.2ej), 0}
__device__ __half   g_hT[HEADS * FOUT * NN];     // transposed h, fp16
__device__ unsigned g_adjb[NN * ADJW];           // adj bitmask
__device__ float    g_part[HEADS * NN * FOUT];   // per-head normalized output

// ---------------- PTX helpers (standard sm_75+ features only) ----------------
__device__ __forceinline__ uint32_t smem_u32(const void* p) {
    uint32_t a;
    asm("{ .reg .u64 t; cvta.to.shared.u64 t, %1; cvt.u32.u64 %0, t; }" : "=r"(a) : "l"(p));
    return a;
}
__device__ __forceinline__ void ldsm4(uint32_t* r, uint32_t addr) {
    asm volatile("ldmatrix.sync.aligned.m8n8.x4.shared.b16 {%0,%1,%2,%3}, [%4];"
                 : "=r"(r[0]), "=r"(r[1]), "=r"(r[2]), "=r"(r[3]) : "r"(addr));
}
__device__ __forceinline__ void mma16816(float* c, const uint32_t* a,
                                         uint32_t b0, uint32_t b1) {
    asm volatile("mma.sync.aligned.m16n8k16.row.col.f32.f16.f16.f32 "
                 "{%0,%1,%2,%3}, {%4,%5,%6,%7}, {%8,%9}, {%0,%1,%2,%3};"
                 : "+f"(c[0]), "+f"(c[1]), "+f"(c[2]), "+f"(c[3])
                 : "r"(a[0]), "r"(a[1]), "r"(a[2]), "r"(a[3]), "r"(b0), "r"(b1));
}
// XOR swizzle: permute 16B chunks within a 128B row by row&7 (conflict-free LDSM)
__device__ __forceinline__ uint32_t swz(int row, int byteInRow) {
    return (uint32_t)(row * 128 + ((((byteInRow >> 4) ^ (row & 7)) << 4) | (byteInRow & 15)));
}

// ---------------- kernel 1: h = x @ W, + fp16 transposed copy ----------------
__global__ void __launch_bounds__(256) gemm_h_kernel(const float* __restrict__ x,
                                                     const float* __restrict__ W) {
    __shared__ float xs[32][FIN];    // 32 KB
    const int n0 = blockIdx.x * 32;
    const int t  = threadIdx.x;

    #pragma unroll
    for (int r = 0; r < 32; ++r) xs[r][t] = x[(n0 + r) * FIN + t];
    __syncthreads();

    float acc[32];
    #pragma unroll
    for (int r = 0; r < 32; ++r) acc[r] = 0.0f;

    for (int k = 0; k < FIN; k += 4) {
        const float w0 = W[(k + 0) * 256 + t];
        const float w1 = W[(k + 1) * 256 + t];
        const float w2 = W[(k + 2) * 256 + t];
        const float w3 = W[(k + 3) * 256 + t];
        #pragma unroll
        for (int r = 0; r < 32; ++r) {
            const float4 xv = *(const float4*)&xs[r][k];
            acc[r] = fmaf(xv.x, w0, acc[r]);
            acc[r] = fmaf(xv.y, w1, acc[r]);
            acc[r] = fmaf(xv.z, w2, acc[r]);
            acc[r] = fmaf(xv.w, w3, acc[r]);
        }
    }
    #pragma unroll
    for (int r = 0; r < 32; ++r) g_h[(n0 + r) * FIN + t] = acc[r];

    // thread t already holds column t (= head*64+f) for rows n0..n0+31 -> direct hT write
    unsigned hp[16];
    #pragma unroll
    for (int r = 0; r < 32; r += 2) {
        const __half h0 = __float2half_rn(acc[r]);
        const __half h1 = __float2half_rn(acc[r + 1]);
        hp[r >> 1] = ((unsigned)__half_as_ushort(h1) << 16) | __half_as_ushort(h0);
    }
    uint4* dh = (uint4*)&g_hT[(size_t)t * NN + n0];
    #pragma unroll
    for (int q = 0; q < 4; ++q)
        dh[q] = make_uint4(hp[4 * q], hp[4 * q + 1], hp[4 * q + 2], hp[4 * q + 3]);
}

// ---------------- kernel 2: e scores + factored exps ----------------
__global__ void __launch_bounds__(256) escore_kernel(const float* __restrict__ a) {
    __shared__ float s1[256], s2[256];
    const int n = blockIdx.x;
    const int t = threadIdx.x;
    const int ff = t & 63;
    const float v = g_h[n * FIN + t];
    s1[t] = v * a[ff];
    s2[t] = v * a[64 + ff];
    __syncthreads();
    #pragma unroll
    for (int off = 32; off >= 1; off >>= 1) {
        if ((t & 63) < off) { s1[t] += s1[t + off]; s2[t] += s2[t + off]; }
        __syncthreads();
    }
    if ((t & 63) == 0) {
        const int hd = t >> 6;
        const float ei = s1[t], ej = s2[t];
        g_i4[n * HEADS + hd] = make_float4(ei, __expf(ei), __expf(0.2f * ei), 0.0f);
        g_j4[n * HEADS + hd] = make_float4(ej, __expf(ej), __expf(0.2f * ej), 0.0f);
    }
}

// ---------------- kernel 2b: pack adj into bitmask ----------------
__global__ void __launch_bounds__(256) adj_pack_kernel(const int* __restrict__ adj) {
    const int row  = blockIdx.x * 8 + (threadIdx.x >> 5);
    const int lane = threadIdx.x & 31;
    const int* ar = adj + (size_t)row * NN;
    for (int k = 0; k < ADJW; ++k) {
        const int v = ar[k * 32 + lane];
        const unsigned m = __ballot_sync(0xffffffffu, v != 0);
        if (lane == 0) g_adjb[row * ADJW + k] = m;
    }
}

// ---------------- kernel 3: mma.sync attention ----------------
// Block = (64 i-rows, head). Per 64-j chunk: gen fp16 W-tile [64x64] (factored
// exp + bitmask, fp32 Z on the side), load fp16 hT tile [64(f) x 64(j)], then
// 8 warps each compute a 16x32 C-tile via m16n8k16 HMMA with fp32 accum.
__global__ void __launch_bounds__(256) gat_mma_kernel() {
    __shared__ __align__(128) __half Wt[ITILE * JCHUNK];   // 8 KB  [i][j] swizzled
    __shared__ __align__(128) __half Ht[FOUT * JCHUNK];    // 8 KB  [f][j] swizzled
    __shared__ float4 esm[ITILE];
    __shared__ float  zsm[ITILE];

    const int t    = threadIdx.x;
    const int lane = t & 31;
    const int w    = t >> 5;
    const int head = blockIdx.y;
    const int i0   = blockIdx.x * ITILE;

    if (t < ITILE) esm[t] = g_i4[(i0 + t) * HEADS + head];

    const uint32_t wtb = smem_u32(Wt);
    const uint32_t htb = smem_u32(Ht);

    // mma tile coords: warp w -> rows (w&3)*16, cols (w>>2)*32
    const int mrow0 = (w & 3) * 16;
    const int ncol0 = (w >> 2) * 32;

    float acc[4][4];
    #pragma unroll
    for (int n = 0; n < 4; ++n)
        #pragma unroll
        for (int k = 0; k < 4; ++k) acc[n][k] = 0.0f;
    float z[8];
    #pragma unroll
    for (int r = 0; r < 8; ++r) z[r] = 0.0f;

    char* WtB = (char*)Wt;
    char* HtB = (char*)Ht;
    __syncthreads();

    for (int c = 0; c < NCHUNK; ++c) {
        const int j0 = c * JCHUNK;

        // ---- gen: W[il][2*lane, 2*lane+1], warp w owns rows {w, w+8, ...} ----
        const float4 jd0 = g_j4[(j0 + 2 * lane) * HEADS + head];
        const float4 jd1 = g_j4[(j0 + 2 * lane + 1) * HEADS + head];
        #pragma unroll
        for (int r = 0; r < 8; ++r) {
            const int il = w + 8 * r;
            const uint2 aw = *(const uint2*)&g_adjb[(size_t)(i0 + il) * ADJW + 2 * c];
            const float4 id = esm[il];
            const unsigned bits = ((lane < 16) ? aw.x : aw.y) >> ((2 * lane) & 31);
            const float s0 = id.x + jd0.x;
            const float s1 = id.x + jd1.x;
            float w0 = (s0 > 0.0f) ? id.y * jd0.y : id.z * jd0.z;
            float w1 = (s1 > 0.0f) ? id.y * jd1.y : id.z * jd1.z;
            w0 = (bits & 1u) ? w0 : 0.0f;
            w1 = (bits & 2u) ? w1 : 0.0f;
            z[r] += w0 + w1;
            *(__half2*)(WtB + swz(il, lane * 4)) = __floats2half2_rn(w0, w1);
        }
        // ---- hT tile loader: row f = t>>2, 32B segment = t&3 ----
        {
            const int row = t >> 2;
            const int seg = t & 3;
            const __half* src = &g_hT[(size_t)(head * FOUT + row) * NN + j0 + seg * 16];
            const uint4 v0 = *(const uint4*)(src);
            const uint4 v1 = *(const uint4*)(src + 8);
            *(uint4*)(HtB + swz(row, seg * 32))      = v0;
            *(uint4*)(HtB + swz(row, seg * 32 + 16)) = v1;
        }
        __syncthreads();

        // ---- mma: 4 k-steps x 4 n-tiles ----
        #pragma unroll
        for (int ks = 0; ks < 4; ++ks) {
            uint32_t af[4];
            {
                const int arow = mrow0 + (lane & 15);
                const int akc  = ks * 2 + (lane >> 4);
                ldsm4(af, wtb + swz(arow, akc * 16));
            }
            #pragma unroll
            for (int np = 0; np < 2; ++np) {
                uint32_t bf[4];
                const int grp  = lane >> 3;
                const int brow = ncol0 + np * 16 + (grp >> 1) * 8 + (lane & 7);
                const int bkc  = ks * 2 + (grp & 1);
                ldsm4(bf, htb + swz(brow, bkc * 16));
                mma16816(acc[np * 2],     af, bf[0], bf[1]);
                mma16816(acc[np * 2 + 1], af, bf[2], bf[3]);
            }
        }
        __syncthreads();
    }

    // ---- Z: reduce across 32 lanes; warp w owns rows {w, w+8, ...} ----
    #pragma unroll
    for (int r = 0; r < 8; ++r) {
        float v = z[r];
        #pragma unroll
        for (int off = 16; off >= 1; off >>= 1)
            v += __shfl_xor_sync(0xffffffffu, v, off);
        if (lane == 0) zsm[w + 8 * r] = v;
    }
    __syncthreads();

    // ---- epilogue: normalize and store per-head output ----
    {
        const int q  = lane >> 2;
        const int i2 = (lane & 3) * 2;
        const int r0 = mrow0 + q;
        const int r1 = mrow0 + q + 8;
        const float iz0 = 1.0f / zsm[r0];
        const float iz1 = 1.0f / zsm[r1];
        float* p0 = g_part + ((size_t)head * NN + i0 + r0) * FOUT + ncol0 + i2;
        float* p1 = g_part + ((size_t)head * NN + i0 + r1) * FOUT + ncol0 + i2;
        #pragma unroll
        for (int nt = 0; nt < 4; ++nt) {
            *(float2*)(p0 + nt * 8) = make_float2(acc[nt][0] * iz0, acc[nt][1] * iz0);
            *(float2*)(p1 + nt * 8) = make_float2(acc[nt][2] * iz1, acc[nt][3] * iz1);
        }
    }
}

// ---------------- kernel 4: mean over heads ----------------
__global__ void __launch_bounds__(256) combine_kernel(float* __restrict__ out) {
    const int idx = blockIdx.x * 256 + threadIdx.x;
    out[idx] = 0.25f * (g_part[idx] + g_part[NF + idx] +
                        g_part[2 * NF + idx] + g_part[3 * NF + idx]);
}

// ---------------- launcher ----------------
extern "C" void kernel_launch(void* const* d_in, const int* in_sizes, int n_in,
                              void* d_out, int out_size) {
    const float* x = nullptr;
    const int*   adj = nullptr;
    const float* W = nullptr;
    const float* a = nullptr;
    for (int i = 0; i < n_in; ++i) {
        switch (in_sizes[i]) {
            case 1048576:  x   = (const float*)d_in[i]; break;
            case 16777216: adj = (const int*)  d_in[i]; break;
            case 65536:    W   = (const float*)d_in[i]; break;
            case 128:      a   = (const float*)d_in[i]; break;
        }
    }
    float* out = (float*)d_out;

    gemm_h_kernel<<<NN / 32, 256>>>(x, W);
    escore_kernel<<<NN, 256>>>(a);
    adj_pack_kernel<<<NN / 8, 256>>>(adj);
    gat_mma_kernel<<<dim3(NN / ITILE, HEADS), 256>>>();
    combine_kernel<<<NF / 256, 256>>>(out);
}

// round 6
// speedup vs baseline: 3.3342x; 1.1186x over previous
#include <cuda_runtime.h>
#include <cuda_fp16.h>
#include <cstdint>

#define NN      4096
#define FIN     256
#define FOUT    64
#define HEADS   4
#define NF      (NN * FOUT)
#define ITILE   64
#define JCHUNK  64
#define NCHUNK  (NN / JCHUNK)   // 64
#define ADJW    (NN / 32)       // 128 words per adj row

// ---------------- device scratch ----------------
__device__ float4   g_i4[NN * HEADS];            // {ei, exp(ei), exp(.2ei), 0}
__device__ float4   g_j4[NN * HEADS];            // {ej, exp(ej), exp(.2ej), 0}
__device__ __half   g_hT[HEADS * FOUT * NN];     // transposed h, fp16
__device__ unsigned g_adjb[NN * ADJW];           // adj bitmask, layout [row][g][k]:
                                                 //   word (g,k) bit l <-> col 128g+4l+k
__device__ float    g_part[HEADS * NN * FOUT];   // per-head normalized output

// ---------------- PTX helpers (standard sm_75+ features only) ----------------
__device__ __forceinline__ uint32_t smem_u32(const void* p) {
    uint32_t a;
    asm("{ .reg .u64 t; cvta.to.shared.u64 t, %1; cvt.u32.u64 %0, t; }" : "=r"(a) : "l"(p));
    return a;
}
__device__ __forceinline__ void ldsm4(uint32_t* r, uint32_t addr) {
    asm volatile("ldmatrix.sync.aligned.m8n8.x4.shared.b16 {%0,%1,%2,%3}, [%4];"
                 : "=r"(r[0]), "=r"(r[1]), "=r"(r[2]), "=r"(r[3]) : "r"(addr));
}
__device__ __forceinline__ void mma16816(float* c, const uint32_t* a,
                                         uint32_t b0, uint32_t b1) {
    asm volatile("mma.sync.aligned.m16n8k16.row.col.f32.f16.f16.f32 "
                 "{%0,%1,%2,%3}, {%4,%5,%6,%7}, {%8,%9}, {%0,%1,%2,%3};"
                 : "+f"(c[0]), "+f"(c[1]), "+f"(c[2]), "+f"(c[3])
                 : "r"(a[0]), "r"(a[1]), "r"(a[2]), "r"(a[3]), "r"(b0), "r"(b1));
}
// XOR swizzle: permute 16B chunks within a 128B row by row&7 (conflict-free LDSM)
__device__ __forceinline__ uint32_t swz(int row, int byteInRow) {
    return (uint32_t)(row * 128 + ((((byteInRow >> 4) ^ (row & 7)) << 4) | (byteInRow & 15)));
}

// ---------------- kernel 1: h = x @ W + fp16 hT + fused e-scores ----------------
__global__ void __launch_bounds__(256) gemm_h_kernel(const float* __restrict__ x,
                                                     const float* __restrict__ W,
                                                     const float* __restrict__ a) {
    __shared__ float xs[32][FIN];    // 32 KB; reused as h-tile for escore phase
    __shared__ float as[128];
    const int n0 = blockIdx.x * 32;
    const int t  = threadIdx.x;

    if (t < 128) as[t] = a[t];
    #pragma unroll
    for (int r = 0; r < 32; ++r) xs[r][t] = x[(n0 + r) * FIN + t];
    __syncthreads();

    float acc[32];
    #pragma unroll
    for (int r = 0; r < 32; ++r) acc[r] = 0.0f;

    for (int k = 0; k < FIN; k += 4) {
        const float w0 = W[(k + 0) * 256 + t];
        const float w1 = W[(k + 1) * 256 + t];
        const float w2 = W[(k + 2) * 256 + t];
        const float w3 = W[(k + 3) * 256 + t];
        #pragma unroll
        for (int r = 0; r < 32; ++r) {
            const float4 xv = *(const float4*)&xs[r][k];
            acc[r] = fmaf(xv.x, w0, acc[r]);
            acc[r] = fmaf(xv.y, w1, acc[r]);
            acc[r] = fmaf(xv.z, w2, acc[r]);
            acc[r] = fmaf(xv.w, w3, acc[r]);
        }
    }

    // thread t holds column t (= head*64+f) for rows n0..n0+31 -> direct hT write
    unsigned hp[16];
    #pragma unroll
    for (int r = 0; r < 32; r += 2) {
        const __half h0 = __float2half_rn(acc[r]);
        const __half h1 = __float2half_rn(acc[r + 1]);
        hp[r >> 1] = ((unsigned)__half_as_ushort(h1) << 16) | __half_as_ushort(h0);
    }
    uint4* dh = (uint4*)&g_hT[(size_t)t * NN + n0];
    #pragma unroll
    for (int q = 0; q < 4; ++q)
        dh[q] = make_uint4(hp[4 * q], hp[4 * q + 1], hp[4 * q + 2], hp[4 * q + 3]);

    // ---- fused escore: stage h-tile in smem, 64-wide dots, exp, store ----
    __syncthreads();
    #pragma unroll
    for (int r = 0; r < 32; ++r) xs[r][t] = acc[r];
    __syncthreads();

    {
        const int r     = t >> 3;        // 0..31
        const int g     = t & 7;
        const int hd    = g >> 1;
        const int which = g & 1;
        const float* av = as + which * 64;
        const float* hr = &xs[r][hd * 64];
        float s = 0.0f;
        #pragma unroll
        for (int f = 0; f < 64; ++f) s = fmaf(hr[f], av[f], s);
        const float4 v = make_float4(s, __expf(s), __expf(0.2f * s), 0.0f);
        if (which == 0) g_i4[(n0 + r) * HEADS + hd] = v;
        else            g_j4[(n0 + r) * HEADS + hd] = v;
    }
}

// ---------------- kernel 2: pack adj into bitmask (vectorized) ----------------
// word (g,k) of a row: bit l <-> adj[row][128g + 4l + k]
__global__ void __launch_bounds__(256) adj_pack_kernel(const int* __restrict__ adj) {
    const int row  = blockIdx.x * 8 + (threadIdx.x >> 5);
    const int lane = threadIdx.x & 31;
    const int4* ar = (const int4*)(adj + (size_t)row * NN);
    uint4* dst = (uint4*)(g_adjb + (size_t)row * ADJW);
    #pragma unroll 4
    for (int g = 0; g < 32; ++g) {
        const int4 v = ar[g * 32 + lane];
        const unsigned p0 = __ballot_sync(0xffffffffu, v.x != 0);
        const unsigned p1 = __ballot_sync(0xffffffffu, v.y != 0);
        const unsigned p2 = __ballot_sync(0xffffffffu, v.z != 0);
        const unsigned p3 = __ballot_sync(0xffffffffu, v.w != 0);
        if (lane == 0) dst[g] = make_uint4(p0, p1, p2, p3);
    }
}

// ---------------- kernel 3: pipelined mma.sync attention ----------------
// Block = (64 i-rows, head). Double-buffered Wt/Ht; prefetch chunk c+1's LDGs
// into registers during chunk c; one __syncthreads per chunk.
__global__ void __launch_bounds__(256, 2) gat_mma_kernel() {
    __shared__ __align__(128) __half Wt[2][ITILE * JCHUNK];   // 2 x 8 KB [i][j] swizzled
    __shared__ __align__(128) __half Ht[2][FOUT * JCHUNK];    // 2 x 8 KB [f][j] swizzled
    __shared__ float4 esm[ITILE];
    __shared__ float  zsm[ITILE];

    const int t    = threadIdx.x;
    const int lane = t & 31;
    const int w    = t >> 5;
    const int head = blockIdx.y;
    const int i0   = blockIdx.x * ITILE;

    if (t < ITILE) esm[t] = g_i4[(i0 + t) * HEADS + head];

    const uint32_t wtb = smem_u32(Wt);
    const uint32_t htb = smem_u32(Ht);

    // mma tile coords: warp w -> rows (w&3)*16, cols (w>>2)*32
    const int mrow0 = (w & 3) * 16;
    const int ncol0 = (w >> 2) * 32;

    // loader coords for Ht
    const int hrow = t >> 2;
    const int hseg = t & 3;
    const __half* hsrc0 = &g_hT[(size_t)(head * FOUT + hrow) * NN + hseg * 16];

    // gen coords: bit/word mapping into g_adjb layout
    const int kbase = (lane & 1) * 2;            // word pair {kbase, kbase+1}
    const int lbit  = lane >> 1;                 // bit within word (低 group half)

    float acc[4][4];
    #pragma unroll
    for (int n = 0; n < 4; ++n)
        #pragma unroll
        for (int k = 0; k < 4; ++k) acc[n][k] = 0.0f;
    float z[8];
    #pragma unroll
    for (int r = 0; r < 8; ++r) z[r] = 0.0f;

    // ---- prefetch registers ----
    float4 jd0, jd1;
    uint2  aw[8];
    uint4  hv0, hv1;

    // prefetch chunk 0
    {
        jd0 = g_j4[(2 * lane) * HEADS + head];
        jd1 = g_j4[(2 * lane + 1) * HEADS + head];
        #pragma unroll
        for (int r = 0; r < 8; ++r) {
            const int il = w + 8 * r;
            aw[r] = *(const uint2*)&g_adjb[(size_t)(i0 + il) * ADJW + kbase];
        }
        hv0 = *(const uint4*)(hsrc0);
        hv1 = *(const uint4*)(hsrc0 + 8);
    }
    __syncthreads();   // esm ready

    for (int c = 0; c < NCHUNK; ++c) {
        const int b = c & 1;
        char* WtB = (char*)Wt[b];
        char* HtB = (char*)Ht[b];
        const int bit = ((c & 1) << 4) + lbit;

        // ---- gen/store from prefetched regs ----
        #pragma unroll
        for (int r = 0; r < 8; ++r) {
            const int il = w + 8 * r;
            const float4 id = esm[il];
            const float s0 = id.x + jd0.x;
            const float s1 = id.x + jd1.x;
            float w0 = (s0 > 0.0f) ? id.y * jd0.y : id.z * jd0.z;
            float w1 = (s1 > 0.0f) ? id.y * jd1.y : id.z * jd1.z;
            w0 = ((aw[r].x >> bit) & 1u) ? w0 : 0.0f;
            w1 = ((aw[r].y >> bit) & 1u) ? w1 : 0.0f;
            z[r] += w0 + w1;
            *(__half2*)(WtB + swz(il, lane * 4)) = __floats2half2_rn(w0, w1);
        }
        *(uint4*)(HtB + swz(hrow, hseg * 32))      = hv0;
        *(uint4*)(HtB + swz(hrow, hseg * 32 + 16)) = hv1;

        // ---- prefetch chunk c+1 (overlaps with barrier + mma) ----
        if (c + 1 < NCHUNK) {
            const int jn = (c + 1) * JCHUNK;
            jd0 = g_j4[(jn + 2 * lane) * HEADS + head];
            jd1 = g_j4[(jn + 2 * lane + 1) * HEADS + head];
            const int gofs = ((c + 1) >> 1) * 4 + kbase;
            #pragma unroll
            for (int r = 0; r < 8; ++r) {
                const int il = w + 8 * r;
                aw[r] = *(const uint2*)&g_adjb[(size_t)(i0 + il) * ADJW + gofs];
            }
            hv0 = *(const uint4*)(hsrc0 + jn);
            hv1 = *(const uint4*)(hsrc0 + jn + 8);
        }
        __syncthreads();

        // ---- mma: 4 k-steps x 4 n-tiles from buffer b ----
        const uint32_t wb = wtb + b * (ITILE * JCHUNK * 2);
        const uint32_t hb = htb + b * (FOUT * JCHUNK * 2);
        #pragma unroll
        for (int ks = 0; ks < 4; ++ks) {
            uint32_t af[4];
            {
                const int arow = mrow0 + (lane & 15);
                const int akc  = ks * 2 + (lane >> 4);
                ldsm4(af, wb + swz(arow, akc * 16));
            }
            #pragma unroll
            for (int np = 0; np < 2; ++np) {
                uint32_t bf[4];
                const int grp  = lane >> 3;
                const int brow = ncol0 + np * 16 + (grp >> 1) * 8 + (lane & 7);
                const int bkc  = ks * 2 + (grp & 1);
                ldsm4(bf, hb + swz(brow, bkc * 16));
                mma16816(acc[np * 2],     af, bf[0], bf[1]);
                mma16816(acc[np * 2 + 1], af, bf[2], bf[3]);
            }
        }
        // no trailing sync: gen(c+1) writes the other buffer
    }

    // ---- Z: reduce across 32 lanes; warp w owns rows {w, w+8, ...} ----
    #pragma unroll
    for (int r = 0; r < 8; ++r) {
        float v = z[r];
        #pragma unroll
        for (int off = 16; off >= 1; off >>= 1)
            v += __shfl_xor_sync(0xffffffffu, v, off);
        if (lane == 0) zsm[w + 8 * r] = v;
    }
    __syncthreads();

    // ---- epilogue: normalize and store per-head output ----
    {
        const int q  = lane >> 2;
        const int i2 = (lane & 3) * 2;
        const int r0 = mrow0 + q;
        const int r1 = mrow0 + q + 8;
        const float iz0 = 1.0f / zsm[r0];
        const float iz1 = 1.0f / zsm[r1];
        float* p0 = g_part + ((size_t)head * NN + i0 + r0) * FOUT + ncol0 + i2;
        float* p1 = g_part + ((size_t)head * NN + i0 + r1) * FOUT + ncol0 + i2;
        #pragma unroll
        for (int nt = 0; nt < 4; ++nt) {
            *(float2*)(p0 + nt * 8) = make_float2(acc[nt][0] * iz0, acc[nt][1] * iz0);
            *(float2*)(p1 + nt * 8) = make_float2(acc[nt][2] * iz1, acc[nt][3] * iz1);
        }
    }
}

// ---------------- kernel 4: mean over heads ----------------
__global__ void __launch_bounds__(256) combine_kernel(float* __restrict__ out) {
    const int idx = blockIdx.x * 256 + threadIdx.x;
    out[idx] = 0.25f * (g_part[idx] + g_part[NF + idx] +
                        g_part[2 * NF + idx] + g_part[3 * NF + idx]);
}

// ---------------- launcher ----------------
extern "C" void kernel_launch(void* const* d_in, const int* in_sizes, int n_in,
                              void* d_out, int out_size) {
    const float* x = nullptr;
    const int*   adj = nullptr;
    const float* W = nullptr;
    const float* a = nullptr;
    for (int i = 0; i < n_in; ++i) {
        switch (in_sizes[i]) {
            case 1048576:  x   = (const float*)d_in[i]; break;
            case 16777216: adj = (const int*)  d_in[i]; break;
            case 65536:    W   = (const float*)d_in[i]; break;
            case 128:      a   = (const float*)d_in[i]; break;
        }
    }
    float* out = (float*)d_out;

    gemm_h_kernel<<<NN / 32, 256>>>(x, W, a);
    adj_pack_kernel<<<NN / 8, 256>>>(adj);
    gat_mma_kernel<<<dim3(NN / ITILE, HEADS), 256>>>();
    combine_kernel<<<NF / 256, 256>>>(out);
}